// round 17
// baseline (speedup 1.0000x reference)
#include <cuda_runtime.h>
#include <cuda_fp16.h>
#include <cstdint>

// out = elu(input @ W)  [reference's softmax(eye-mask) == Identity exactly]
// fp32 GEMM M=8192 N=2048 K=2048, single fp16 term on mma.sync.m16n8k16
// (measured rel_err 3.0e-4 < 1e-3).
// R16: fold A fp32->fp16 conversion INTO the GEMM fill (deletes conv_a and
//   its 96MB HBM round-trip): LDG.128 fp32 -> F2FP pack -> STS.64, software-
//   pipelined across ks slices (LDG batch / compute ks1 / STS+LDG / ks2 /
//   STS / ks3) so LDG latency hides under MMA trains. cp.async groups now
//   carry only B; A visibility via STS + the per-iter barrier.
//   conv kernel is W-transpose only (~5us). Platform: R15 (occ-2, CTA
//   128x128, 8 warps, warp 64x32, 3-stage static unroll, tensor 73%).

#define GM 8192
#define GN 2048
#define GK 2048

#define BM 128
#define BN 128
#define BK 64
#define NTHREADS 256
#define NCHUNK (GK / BK)   // 32

// ---------------- scratch (fp16 B only; A converts inline) ----------------
__device__ __half g_Bh[(size_t)GN * GK];   // W^T, K-major rows

// ---------------- smem stage layout ----------------
#define SA 0
#define SB 16384
#define STAGE_BYTES 32768
#define NSTAGE 3
#define SMEM_TOTAL (NSTAGE * STAGE_BYTES)   // 98304/CTA; x2 CTAs = 192KB/SM

__device__ __forceinline__ uint32_t smem_u32(const void* p) {
    uint32_t a;
    asm("{ .reg .u64 t; cvta.to.shared.u64 t, %1; cvt.u32.u64 %0, t; }" : "=r"(a) : "l"(p));
    return a;
}
__device__ __forceinline__ void cp16(uint32_t dst, const void* src) {
    asm volatile("cp.async.cg.shared.global [%0], [%1], 16;" :: "r"(dst), "l"(src));
}
__device__ __forceinline__ void cp_commit() {
    asm volatile("cp.async.commit_group;" ::: "memory");
}
__device__ __forceinline__ void cp_wait1() {
    asm volatile("cp.async.wait_group 1;" ::: "memory");
}
__device__ __forceinline__ void ldsm4(uint32_t addr, uint32_t& r0, uint32_t& r1,
                                      uint32_t& r2, uint32_t& r3) {
    asm volatile("ldmatrix.sync.aligned.m8n8.x4.shared.b16 {%0,%1,%2,%3}, [%4];"
                 : "=r"(r0), "=r"(r1), "=r"(r2), "=r"(r3) : "r"(addr));
}
__device__ __forceinline__ void mma16816(float& d0, float& d1, float& d2, float& d3,
                                         uint32_t a0, uint32_t a1, uint32_t a2, uint32_t a3,
                                         uint32_t b0, uint32_t b1) {
    asm volatile(
        "mma.sync.aligned.m16n8k16.row.col.f32.f16.f16.f32 "
        "{%0,%1,%2,%3}, {%4,%5,%6,%7}, {%8,%9}, {%0,%1,%2,%3};"
        : "+f"(d0), "+f"(d1), "+f"(d2), "+f"(d3)
        : "r"(a0), "r"(a1), "r"(a2), "r"(a3), "r"(b0), "r"(b1));
}
__device__ __forceinline__ void sts8(uint32_t addr, uint32_t lo, uint32_t hi) {
    asm volatile("st.shared.v2.b32 [%0], {%1,%2};" :: "r"(addr), "r"(lo), "r"(hi));
}
__device__ __forceinline__ uint32_t pack2(float x, float y) {
    __half2 h = __float22half2_rn(make_float2(x, y));
    return *reinterpret_cast<uint32_t*>(&h);
}
__device__ __forceinline__ float elu_f(float x) { return x > 0.0f ? x : expm1f(x); }

// ---------------- W conversion kernel (transpose + fp16) ----------------
__global__ __launch_bounds__(256) void conv_kernel(const float* __restrict__ B) {
    __shared__ float tile[32][33];
    int b = blockIdx.x;                   // 0..4095
    int tid = threadIdx.x;
    int n0 = (b & 63) * 32;
    int k0 = (b >> 6) * 32;
    int tx = tid & 31, ty = tid >> 5;     // read phase (32,8)
    #pragma unroll
    for (int j = 0; j < 32; j += 8)
        tile[ty + j][tx] = B[(size_t)(k0 + ty + j) * GN + n0 + tx];
    __syncthreads();
    int kp = tid & 15, nl = tid >> 4;     // write phase: half2 along K
    #pragma unroll
    for (int j = 0; j < 32; j += 16) {
        int n = nl + j;
        __half2 h = __half2(__float2half(tile[kp * 2][n]),
                            __float2half(tile[kp * 2 + 1][n]));
        *reinterpret_cast<__half2*>(g_Bh + (size_t)(n0 + n) * GK + k0 + kp * 2) = h;
    }
}

// ---------------- B stage fill (one BK=64 chunk) ----------------
__device__ __forceinline__ void fillB(uint32_t sbase, uint32_t s0,
                                      const char* pB, int kc) {
    const size_t koff = (size_t)kc * 128;
    #pragma unroll
    for (int j = 0; j < 4; j++)
        cp16(sbase + SB + s0 + j * 4096, pB + koff + (size_t)j * 131072);
}

// ---------------- main GEMM kernel ----------------
__global__ __launch_bounds__(NTHREADS, 2)
void gat_mma_kernel(const float* __restrict__ A, float* __restrict__ C) {
    extern __shared__ char smem[];
    uint32_t sb = smem_u32(smem);
    const int tid  = threadIdx.x;
    const int wid  = tid >> 5;
    const int lane = tid & 31;
    const int m0 = blockIdx.y * BM;
    const int n0 = blockIdx.x * BN;
    const int warp_m = wid & 1;    // 2 M-tiles of 64
    const int warp_n = wid >> 1;   // 4 N-tiles of 32

    // ---- B fill addressing (cp.async; SW128 mask invariant across strides)
    const uint32_t s0 = (uint32_t)((tid >> 3) * 128 +
                        (((tid & 7) * 16) ^ (((tid >> 3) & 7) << 4)));
    const char* pB = (const char*)g_Bh + (size_t)(n0 + (tid >> 3)) * 4096 + (tid & 7) * 16;

    // ---- A inline-convert fill addressing ----
    // thread = (row-slot fr = tid>>4 in 0..15, float4 lane fc = tid&15);
    // per chunk 8 rows-groups j: row = fr + 16j (row&7 == fr&7, j-invariant).
    const int fr = tid >> 4;
    const int fc = tid & 15;
    const uint32_t stsA0 = (uint32_t)(fr * 128 + ((fc * 8) ^ ((fr & 7) << 4)));
    const float4* pA4 = reinterpret_cast<const float4*>(
                            A + (size_t)(m0 + fr) * GK) + fc;
    // j stride: 16 rows * 2048 floats / 4 = 8192 float4; chunk stride: 16 float4

    float acc[4][4][4];
    #pragma unroll
    for (int i = 0; i < 4; i++)
        #pragma unroll
        for (int j = 0; j < 4; j++)
            #pragma unroll
            for (int t = 0; t < 4; t++) acc[i][j][t] = 0.0f;

    // per-lane swizzled ldsm bases
    const int a_row_l = lane & 15;
    const uint32_t a_kb = (uint32_t)((lane >> 4) << 4);
    const int b_j = lane >> 3;
    const int b_row_l = (lane & 7) + ((b_j >> 1) << 3);
    const uint32_t b_kb = (uint32_t)((b_j & 1) << 4);

    uint32_t baseA[4], xA[4];
    #pragma unroll
    for (int mt = 0; mt < 4; mt++) {
        int row = warp_m * 64 + mt * 16 + a_row_l;
        baseA[mt] = (uint32_t)(row << 7);
        xA[mt]    = (uint32_t)((row & 7) << 4);
    }
    uint32_t baseB[2], xB[2];
    #pragma unroll
    for (int np = 0; np < 2; np++) {
        int row = warp_n * 32 + np * 16 + b_row_l;
        baseB[np] = (uint32_t)(row << 7);
        xB[np]    = (uint32_t)((row & 7) << 4);
    }

    // one ks-slice of compute (4 ldsm + 16 MMA; A frags double-buffered)
    auto compute_ks = [&](uint32_t stage, int ks) {
        const uint32_t kb = (uint32_t)(ks * 32);
        uint32_t bh[4][2];
        #pragma unroll
        for (int np = 0; np < 2; np++) {
            uint32_t ad = stage + SB + baseB[np] + ((kb + b_kb) ^ xB[np]);
            uint32_t r0, r1, r2, r3;
            ldsm4(ad, r0, r1, r2, r3);
            bh[np * 2 + 0][0] = r0; bh[np * 2 + 0][1] = r1;
            bh[np * 2 + 1][0] = r2; bh[np * 2 + 1][1] = r3;
        }
        uint32_t ah[2][4];
        {
            uint32_t ad = stage + SA + baseA[0] + ((kb + a_kb) ^ xA[0]);
            ldsm4(ad, ah[0][0], ah[0][1], ah[0][2], ah[0][3]);
        }
        #pragma unroll
        for (int mt = 0; mt < 4; mt++) {
            const int cb = mt & 1;
            if (mt < 3) {
                const int nb = (mt + 1) & 1;
                uint32_t ad = stage + SA + baseA[mt + 1] + ((kb + a_kb) ^ xA[mt + 1]);
                ldsm4(ad, ah[nb][0], ah[nb][1], ah[nb][2], ah[nb][3]);
            }
            #pragma unroll
            for (int nt = 0; nt < 4; nt++)
                mma16816(acc[mt][nt][0], acc[mt][nt][1], acc[mt][nt][2], acc[mt][nt][3],
                         ah[cb][0], ah[cb][1], ah[cb][2], ah[cb][3],
                         bh[nt][0], bh[nt][1]);
        }
    };

    const uint32_t st0 = sb, st1 = sb + STAGE_BYTES, st2 = sb + 2 * STAGE_BYTES;
    const uint32_t stA[3] = { st0 + SA + stsA0, st1 + SA + stsA0, st2 + SA + stsA0 };

    // prologue: B cp.async for chunks 0,1,2 (3 groups), then A convert inline
    fillB(st0, s0, pB, 0); cp_commit();
    fillB(st1, s0, pB, 1); cp_commit();
    fillB(st2, s0, pB, 2); cp_commit();
    #pragma unroll
    for (int s = 0; s < 3; s++) {
        const float4* p = pA4 + s * 16;
        #pragma unroll
        for (int j = 0; j < 8; j++) {
            float4 t = p[(size_t)j * 8192];
            sts8(stA[s] + j * 2048, pack2(t.x, t.y), pack2(t.z, t.w));
        }
    }

    // pipeline iteration. A STS of chunk k+2 (iter k) precede the barriers at
    // iters k+1 and k+2 tops -> visible to all warps before chunk k+2 is read.
    auto iter = [&](int k, uint32_t stage, uint32_t prevslot, bool dofill) {
        cp_wait1();
        __syncthreads();
        compute_ks(stage, 0);
        const int kc = k + 2;
        const float4* pc = pA4 + kc * 16;
        const uint32_t sbase = prevslot + SA + stsA0;
        if (dofill) fillB(prevslot, s0, pB, kc);
        if (k >= 1) cp_commit();
        float4 t[4];
        if (dofill) {
            #pragma unroll
            for (int j = 0; j < 4; j++) t[j] = pc[(size_t)j * 8192];
        }
        compute_ks(stage, 1);
        if (dofill) {
            #pragma unroll
            for (int j = 0; j < 4; j++)
                sts8(sbase + j * 2048, pack2(t[j].x, t[j].y), pack2(t[j].z, t[j].w));
            #pragma unroll
            for (int j = 0; j < 4; j++) t[j] = pc[(size_t)(4 + j) * 8192];
        }
        compute_ks(stage, 2);
        if (dofill) {
            #pragma unroll
            for (int j = 0; j < 4; j++)
                sts8(sbase + (4 + j) * 2048, pack2(t[j].x, t[j].y), pack2(t[j].z, t[j].w));
        }
        compute_ks(stage, 3);
    };

    iter(0, st0, st2, false);
    iter(1, st1, st0, true);
    iter(2, st2, st1, true);
    #pragma unroll 1
    for (int ko = 3; ko < 30; ko += 3) {
        iter(ko,     st0, st2, true);
        iter(ko + 1, st1, st0, true);
        iter(ko + 2, st2, st1, true);
    }
    iter(30, st0, st2, false);   // commit-only (empty group)
    iter(31, st1, st0, false);   // commit-only (empty group)

    // ---------------- epilogue: fused elu, float2 stores ----------------
    const int gp  = lane >> 2;
    const int tg2 = (lane & 3) * 2;
    #pragma unroll
    for (int mt = 0; mt < 4; mt++) {
        int mrow = m0 + warp_m * 64 + mt * 16 + gp;
        #pragma unroll
        for (int nt = 0; nt < 4; nt++) {
            int ncol = n0 + warp_n * 32 + nt * 8 + tg2;
            float2 v0, v1;
            v0.x = elu_f(acc[mt][nt][0]);
            v0.y = elu_f(acc[mt][nt][1]);
            v1.x = elu_f(acc[mt][nt][2]);
            v1.y = elu_f(acc[mt][nt][3]);
            *reinterpret_cast<float2*>(C + (size_t)mrow * GN + ncol) = v0;
            *reinterpret_cast<float2*>(C + (size_t)(mrow + 8) * GN + ncol) = v1;
        }
    }
}

// ---------------- launch ----------------
extern "C" void kernel_launch(void* const* d_in, const int* in_sizes, int n_in,
                              void* d_out, int out_size) {
    const float* input = (const float*)d_in[0];   // [8192, 2048]
    const float* W     = (const float*)d_in[2];   // [2048, 2048]
    float*       out   = (float*)d_out;

    cudaFuncSetAttribute(gat_mma_kernel,
                         cudaFuncAttributeMaxDynamicSharedMemorySize, SMEM_TOTAL);

    conv_kernel<<<4096, 256>>>(W);
    gat_mma_kernel<<<dim3(GN / BN, GM / BM), NTHREADS, SMEM_TOTAL>>>(input, out);
}